// round 4
// baseline (speedup 1.0000x reference)
#include <cuda_runtime.h>
#include <cuda_bf16.h>
#include <cstdint>

// Problem constants (fixed by the dataset)
static constexpr int NN  = 100000;   // nodes
static constexpr int NE  = 600000;   // edges

// ---------------- scratch (device globals: no allocations allowed) ----------
__device__ int   g_is64;
__device__ int   g_src[NE];
__device__ int   g_dst[NE];
__device__ float g_deg[NN];
__device__ float g_dinv[NN];
__device__ float g_norm[NE];
__device__ float g_h1[(size_t)NN * 128];   // x @ W1 (raw)
__device__ float g_a1[(size_t)NN * 128];   // aggregated layer-1
__device__ float g_h2[(size_t)NN * 64];    // relu(a1+b1) @ W2 (raw)
__device__ __nv_bfloat16 g_xh[(size_t)NN * 128];
__device__ __nv_bfloat16 g_xl[(size_t)NN * 128];
__device__ __nv_bfloat16 g_ah[(size_t)NN * 128];
__device__ __nv_bfloat16 g_al[(size_t)NN * 128];
__device__ __nv_bfloat16 g_w1h[128 * 128];  // [n][k] (transposed)
__device__ __nv_bfloat16 g_w1l[128 * 128];
__device__ __nv_bfloat16 g_w2h[64 * 128];
__device__ __nv_bfloat16 g_w2l[64 * 128];

// ---------------- helpers ----------------------------------------------------
__device__ __forceinline__ uint32_t smem_to_u32(const void* p) {
    uint32_t a;
    asm("{ .reg .u64 t; cvta.to.shared.u64 t, %1; cvt.u32.u64 %0, t; }"
        : "=r"(a) : "l"(p));
    return a;
}
// XOR-swizzle a byte offset within a [rows][256B] tile (16B chunks x row%8)
__device__ __forceinline__ int swz(int o) { return o ^ ((o >> 4) & 0x70); }

__device__ __forceinline__ void ldm_x4(uint32_t* r, uint32_t addr) {
    asm volatile("ldmatrix.sync.aligned.m8n8.x4.shared.b16 {%0,%1,%2,%3}, [%4];"
                 : "=r"(r[0]), "=r"(r[1]), "=r"(r[2]), "=r"(r[3]) : "r"(addr));
}
__device__ __forceinline__ void ldm_x2(uint32_t* r, uint32_t addr) {
    asm volatile("ldmatrix.sync.aligned.m8n8.x2.shared.b16 {%0,%1}, [%2];"
                 : "=r"(r[0]), "=r"(r[1]) : "r"(addr));
}
__device__ __forceinline__ void mma_bf16(float* c, const uint32_t* a, const uint32_t* b) {
    asm volatile(
        "mma.sync.aligned.m16n8k16.row.col.f32.bf16.bf16.f32 "
        "{%0,%1,%2,%3}, {%4,%5,%6,%7}, {%8,%9}, {%0,%1,%2,%3};"
        : "+f"(c[0]), "+f"(c[1]), "+f"(c[2]), "+f"(c[3])
        : "r"(a[0]), "r"(a[1]), "r"(a[2]), "r"(a[3]), "r"(b[0]), "r"(b[1]));
}

// ---------------- edge-index width detection + normalization ----------------
__global__ void detect_kernel(const void* ei) {
    const int* p = (const int*)ei;
    bool z = (p[2 * threadIdx.x + 1] == 0);
    unsigned m = __ballot_sync(0xffffffffu, z);
    __shared__ int ok[2];
    if ((threadIdx.x & 31) == 0) ok[threadIdx.x >> 5] = (m == 0xffffffffu) ? 1 : 0;
    __syncthreads();
    if (threadIdx.x == 0) g_is64 = ok[0] & ok[1];
}

__global__ void convert_edges(const void* ei) {
    int e = blockIdx.x * blockDim.x + threadIdx.x;
    if (e >= NE) return;
    if (g_is64) {
        const long long* p = (const long long*)ei;
        g_src[e] = (int)p[e];
        g_dst[e] = (int)p[e + NE];
    } else {
        const int* p = (const int*)ei;
        g_src[e] = p[e];
        g_dst[e] = p[e + NE];
    }
}

__global__ void zero_deg_kernel() {
    int i = blockIdx.x * blockDim.x + threadIdx.x;
    if (i < NN) g_deg[i] = 0.0f;
}
__global__ void deg_accum_kernel() {
    int e = blockIdx.x * blockDim.x + threadIdx.x;
    if (e < NE) atomicAdd(&g_deg[g_dst[e]], 1.0f);
}
__global__ void dinv_kernel() {
    int i = blockIdx.x * blockDim.x + threadIdx.x;
    if (i < NN) g_dinv[i] = 1.0f / sqrtf(g_deg[i] + 1.0f);
}
__global__ void norm_kernel() {
    int e = blockIdx.x * blockDim.x + threadIdx.x;
    if (e < NE) g_norm[e] = g_dinv[g_src[e]] * g_dinv[g_dst[e]];
}

// ---------------- fp32 -> bf16 hi/lo splits ----------------------------------
__device__ __forceinline__ uint32_t pack_bf2(__nv_bfloat16 a, __nv_bfloat16 b) {
    __nv_bfloat162 t = __halves2bfloat162(a, b);
    return *reinterpret_cast<uint32_t*>(&t);
}
__device__ __forceinline__ void split1(float v, __nv_bfloat16& h, __nv_bfloat16& l) {
    h = __float2bfloat16(v);
    l = __float2bfloat16(v - __bfloat162float(h));
}

// W [K=128][Ncols] row-major -> out[n][k] (transposed), split hi/lo
__global__ void wconv_kernel(const float* __restrict__ W, int Ncols,
                             __nv_bfloat16* __restrict__ oh, __nv_bfloat16* __restrict__ ol) {
    int i = blockIdx.x * blockDim.x + threadIdx.x;
    if (i >= 128 * Ncols) return;
    int k = i / Ncols, n = i % Ncols;
    __nv_bfloat16 h, l;
    split1(W[i], h, l);
    oh[n * 128 + k] = h;
    ol[n * 128 + k] = l;
}

__global__ void split_x_kernel(const float* __restrict__ x) {
    int idx = blockIdx.x * blockDim.x + threadIdx.x;  // over NN*32 float4s
    if (idx >= NN * 32) return;
    float4 v = ((const float4*)x)[idx];
    __nv_bfloat16 h0, h1, h2, h3, l0, l1, l2, l3;
    split1(v.x, h0, l0); split1(v.y, h1, l1);
    split1(v.z, h2, l2); split1(v.w, h3, l3);
    ((uint2*)g_xh)[idx] = make_uint2(pack_bf2(h0, h1), pack_bf2(h2, h3));
    ((uint2*)g_xl)[idx] = make_uint2(pack_bf2(l0, l1), pack_bf2(l2, l3));
}

// relu(a1 + b1) -> g_ah/g_al
__global__ void split_a_kernel(const float* __restrict__ b1) {
    int idx = blockIdx.x * blockDim.x + threadIdx.x;  // over NN*32 float4s
    if (idx >= NN * 32) return;
    int colq = (idx & 31) * 4;
    float4 v = ((const float4*)g_a1)[idx];
    float4 bb = *(const float4*)(b1 + colq);
    v.x = fmaxf(v.x + bb.x, 0.f); v.y = fmaxf(v.y + bb.y, 0.f);
    v.z = fmaxf(v.z + bb.z, 0.f); v.w = fmaxf(v.w + bb.w, 0.f);
    __nv_bfloat16 h0, h1, h2, h3, l0, l1, l2, l3;
    split1(v.x, h0, l0); split1(v.y, h1, l1);
    split1(v.z, h2, l2); split1(v.w, h3, l3);
    ((uint2*)g_ah)[idx] = make_uint2(pack_bf2(h0, h1), pack_bf2(h2, h3));
    ((uint2*)g_al)[idx] = make_uint2(pack_bf2(l0, l1), pack_bf2(l2, l3));
}

// ---------------- HMMA GEMM: C[M,NDIM] = A[M,128] @ W[128,NDIM] --------------
// A as bf16 hi/lo (row-major K), B as [NDIM][128] bf16 hi/lo.
// 3 passes: Ah*Bh + Ah*Bl + Al*Bh, fp32 accum.
// Epilogue: C raw; Cs = C * dinv[row]^2 (+ cbias when non-null).
template <int NDIM>
__global__ void __launch_bounds__(256)
mma_gemm(const __nv_bfloat16* __restrict__ Ah, const __nv_bfloat16* __restrict__ Al,
         const __nv_bfloat16* __restrict__ Bh, const __nv_bfloat16* __restrict__ Bl,
         float* __restrict__ C, float* __restrict__ Cs,
         const float* __restrict__ cbias, int M) {
    extern __shared__ char smem[];
    constexpr int WARP_N = NDIM / 2;   // 64 or 32
    constexpr int NT_N = WARP_N / 8;   // 8 or 4
    constexpr int A_BYTES = 128 * 256;
    constexpr int B_BYTES = NDIM * 256;

    const uint32_t sA = smem_to_u32(smem);
    const uint32_t sB0 = sA + A_BYTES;
    const uint32_t sB1 = sB0 + B_BYTES;

    const int tid = threadIdx.x, wid = tid >> 5, lane = tid & 31;
    const int warp_row = wid & 3, warp_col = wid >> 2;
    const int rowBase = blockIdx.x * 128;
    const int vr = (M - rowBase < 128) ? (M - rowBase) : 128;

    // tile loader: global [rows][128] bf16 -> swizzled smem
    auto load_tile = [&](const __nv_bfloat16* g, int rows, int valid, uint32_t off) {
        for (int idx = tid; idx < rows * 16; idx += 256) {
            int row = idx >> 4, c = idx & 15;
            uint4 v = make_uint4(0, 0, 0, 0);
            if (row < valid) v = *(const uint4*)(g + (size_t)row * 128 + c * 8);
            *(uint4*)(smem + (off - sA) + swz(row * 256 + c * 16)) = v;
        }
    };

    load_tile(Ah + (size_t)rowBase * 128, 128, vr, sA);
    load_tile(Bh, NDIM, NDIM, sB0);
    load_tile(Bl, NDIM, NDIM, sB1);
    __syncthreads();

    float acc[2][NT_N][4];
    #pragma unroll
    for (int i = 0; i < 2; i++)
        #pragma unroll
        for (int j = 0; j < NT_N; j++)
            #pragma unroll
            for (int q = 0; q < 4; q++) acc[i][j][q] = 0.0f;

    // per-lane ldmatrix addressing constants
    const int at = lane >> 3;                 // 0..3: A quad-tile index
    const int ar = lane & 7;
    const int aRow0 = warp_row * 32 + ar + (at & 1) * 8;  // + mi*16
    const int aKt = (at >> 1) * 8;
    const int l15 = lane & 15;
    const int bt = l15 >> 3, br = l15 & 7;
    const int bN0 = warp_col * WARP_N + br;   // + ni*8
    const int bKt = bt * 8;

    auto run_pass = [&](uint32_t aBase, uint32_t bBase) {
        #pragma unroll
        for (int ks = 0; ks < 8; ks++) {
            uint32_t a[2][4];
            #pragma unroll
            for (int mi = 0; mi < 2; mi++) {
                int row = aRow0 + mi * 16;
                int byte = row * 256 + (ks * 16 + aKt) * 2;
                ldm_x4(a[mi], aBase + swz(byte));
            }
            uint32_t b[NT_N][2];
            #pragma unroll
            for (int ni = 0; ni < NT_N; ni++) {
                int n = bN0 + ni * 8;
                int byte = n * 256 + (ks * 16 + bKt) * 2;
                ldm_x2(b[ni], bBase + swz(byte));
            }
            #pragma unroll
            for (int mi = 0; mi < 2; mi++)
                #pragma unroll
                for (int ni = 0; ni < NT_N; ni++)
                    mma_bf16(acc[mi][ni], a[mi], b[ni]);
        }
    };

    run_pass(sA, sB0);   // Ah * Bh
    run_pass(sA, sB1);   // Ah * Bl
    __syncthreads();
    load_tile(Al + (size_t)rowBase * 128, 128, vr, sA);
    __syncthreads();
    run_pass(sA, sB0);   // Al * Bh

    // epilogue
    const int erow0 = rowBase + warp_row * 32 + (lane >> 2);
    const int ecol0 = warp_col * WARP_N + (lane & 3) * 2;
    #pragma unroll
    for (int mi = 0; mi < 2; mi++) {
        #pragma unroll
        for (int p = 0; p < 2; p++) {
            int row = erow0 + mi * 16 + p * 8;
            if (row >= M) continue;
            float d = g_dinv[row];
            float w = d * d;
            #pragma unroll
            for (int ni = 0; ni < NT_N; ni++) {
                int col = ecol0 + ni * 8;
                float2 v = make_float2(acc[mi][ni][2 * p], acc[mi][ni][2 * p + 1]);
                *(float2*)(C + (size_t)row * NDIM + col) = v;
                float2 s;
                if (cbias) {
                    s.x = v.x * w + __ldg(cbias + col);
                    s.y = v.y * w + __ldg(cbias + col + 1);
                } else {
                    s.x = v.x * w;
                    s.y = v.y * w;
                }
                *(float2*)(Cs + (size_t)row * NDIM + col) = s;
            }
        }
    }
}

// ---------------- edge aggregation -------------------------------------------
__global__ void agg_edges128(const float* __restrict__ h, float* __restrict__ out) {
    int t = blockIdx.x * blockDim.x + threadIdx.x;
    int e = t >> 5;
    int lane = t & 31;
    if (e >= NE) return;
    int s = g_src[e];
    int d = g_dst[e];
    float nm = g_norm[e];
    float4 v = ((const float4*)(h + (size_t)s * 128))[lane];
    float* o = out + (size_t)d * 128 + lane * 4;
    atomicAdd(o + 0, v.x * nm);
    atomicAdd(o + 1, v.y * nm);
    atomicAdd(o + 2, v.z * nm);
    atomicAdd(o + 3, v.w * nm);
}

__global__ void agg_edges64(const float* __restrict__ h, float* __restrict__ out) {
    int t = blockIdx.x * blockDim.x + threadIdx.x;
    int e = t >> 4;
    int lane = t & 15;
    if (e >= NE) return;
    int s = g_src[e];
    int d = g_dst[e];
    float nm = g_norm[e];
    float4 v = ((const float4*)(h + (size_t)s * 64))[lane];
    float* o = out + (size_t)d * 64 + lane * 4;
    atomicAdd(o + 0, v.x * nm);
    atomicAdd(o + 1, v.y * nm);
    atomicAdd(o + 2, v.z * nm);
    atomicAdd(o + 3, v.w * nm);
}

// ---------------- launcher ---------------------------------------------------
extern "C" void kernel_launch(void* const* d_in, const int* in_sizes, int n_in,
                              void* d_out, int out_size) {
    const float* x  = (const float*)d_in[0];
    const void*  ei = d_in[1];
    const float* W1 = (const float*)d_in[2];
    const float* b1 = (const float*)d_in[3];
    const float* W2 = (const float*)d_in[4];
    const float* b2 = (const float*)d_in[5];
    float* out = (float*)d_out;

    float *h1, *a1, *h2;
    __nv_bfloat16 *xh, *xl, *ah, *al, *w1h, *w1l, *w2h, *w2l;
    cudaGetSymbolAddress((void**)&h1, g_h1);
    cudaGetSymbolAddress((void**)&a1, g_a1);
    cudaGetSymbolAddress((void**)&h2, g_h2);
    cudaGetSymbolAddress((void**)&xh, g_xh);
    cudaGetSymbolAddress((void**)&xl, g_xl);
    cudaGetSymbolAddress((void**)&ah, g_ah);
    cudaGetSymbolAddress((void**)&al, g_al);
    cudaGetSymbolAddress((void**)&w1h, g_w1h);
    cudaGetSymbolAddress((void**)&w1l, g_w1l);
    cudaGetSymbolAddress((void**)&w2h, g_w2h);
    cudaGetSymbolAddress((void**)&w2l, g_w2l);

    constexpr int SMEM1 = 128 * 256 + 2 * 128 * 256;  // A + Bh + Bl = 98304
    constexpr int SMEM2 = 128 * 256 + 2 * 64 * 256;   // 65536
    cudaFuncSetAttribute(mma_gemm<128>, cudaFuncAttributeMaxDynamicSharedMemorySize, SMEM1);
    cudaFuncSetAttribute(mma_gemm<64>,  cudaFuncAttributeMaxDynamicSharedMemorySize, SMEM2);

    const int T = 256;
    // 1. edge preprocessing
    detect_kernel<<<1, 64>>>(ei);
    convert_edges<<<(NE + T - 1) / T, T>>>(ei);
    zero_deg_kernel<<<(NN + T - 1) / T, T>>>();
    deg_accum_kernel<<<(NE + T - 1) / T, T>>>();
    dinv_kernel<<<(NN + T - 1) / T, T>>>();
    norm_kernel<<<(NE + T - 1) / T, T>>>();

    // 2. bf16 hi/lo splits of weights and x
    wconv_kernel<<<(128 * 128 + T - 1) / T, T>>>(W1, 128, w1h, w1l);
    wconv_kernel<<<(128 * 64 + T - 1) / T, T>>>(W2, 64, w2h, w2l);
    split_x_kernel<<<(NN * 32 + T - 1) / T, T>>>(x);

    // 3. layer 1: h1 = x @ W1 (epilogue writes a1 = h1*dinv^2), then edges
    const int GRID = (NN + 127) / 128;  // 782
    mma_gemm<128><<<GRID, 256, SMEM1>>>(xh, xl, w1h, w1l, h1, a1, nullptr, NN);
    agg_edges128<<<(NE * 32 + T - 1) / T, T>>>(h1, a1);

    // 4. layer 2: A = relu(a1+b1); h2 = A @ W2 (epilogue writes out = h2*dinv^2 + b2)
    split_a_kernel<<<(NN * 32 + T - 1) / T, T>>>(b1);
    mma_gemm<64><<<GRID, 256, SMEM2>>>(ah, al, w2h, w2l, h2, out, b2, NN);
    agg_edges64<<<(NE * 16 + T - 1) / T, T>>>(h2, out);
}

// round 8
// speedup vs baseline: 1.4253x; 1.4253x over previous
#include <cuda_runtime.h>
#include <cstdint>

// Problem constants (fixed by the dataset)
static constexpr int NN  = 100000;   // nodes
static constexpr int NE  = 600000;   // edges
static constexpr int KD  = 128;      // in_dim == hidden (K of both GEMMs)
static constexpr int HID = 128;      // hidden width
static constexpr int FO  = 64;       // out width

// ---------------- scratch (device globals: no allocations allowed) ----------
__device__ int   g_is64;
__device__ int   g_src[NE];
__device__ int   g_dst[NE];
__device__ float g_deg[NN];
__device__ float g_dinv[NN];
__device__ float g_norm[NE];
__device__ float g_h1[(size_t)NN * HID];   // x @ W1
__device__ float g_a1[(size_t)NN * HID];   // aggregated layer-1 (pre bias/relu)
__device__ float g_h2[(size_t)NN * FO];    // relu(a1+b1) @ W2

// ---------------- vectorized global reduction --------------------------------
__device__ __forceinline__ void red_v4(float* addr, float4 v) {
    asm volatile("red.global.add.v4.f32 [%0], {%1, %2, %3, %4};"
                 :: "l"(addr), "f"(v.x), "f"(v.y), "f"(v.z), "f"(v.w)
                 : "memory");
}

// ---------------- edge-index width detection + normalization ----------------
__global__ void detect_kernel(const void* ei) {
    const int* p = (const int*)ei;
    bool z = (p[2 * threadIdx.x + 1] == 0);
    unsigned m = __ballot_sync(0xffffffffu, z);
    __shared__ int ok[2];
    if ((threadIdx.x & 31) == 0) ok[threadIdx.x >> 5] = (m == 0xffffffffu) ? 1 : 0;
    __syncthreads();
    if (threadIdx.x == 0) g_is64 = ok[0] & ok[1];
}

__global__ void convert_edges(const void* ei) {
    int e = blockIdx.x * blockDim.x + threadIdx.x;
    if (e >= NE) return;
    if (g_is64) {
        const long long* p = (const long long*)ei;
        g_src[e] = (int)p[e];
        g_dst[e] = (int)p[e + NE];
    } else {
        const int* p = (const int*)ei;
        g_src[e] = p[e];
        g_dst[e] = p[e + NE];
    }
}

// ---------------- degree / normalization ------------------------------------
__global__ void zero_deg_kernel() {
    int i = blockIdx.x * blockDim.x + threadIdx.x;
    if (i < NN) g_deg[i] = 0.0f;
}

__global__ void deg_accum_kernel() {
    int e = blockIdx.x * blockDim.x + threadIdx.x;
    if (e < NE) atomicAdd(&g_deg[g_dst[e]], 1.0f);
}

__global__ void dinv_kernel() {
    int i = blockIdx.x * blockDim.x + threadIdx.x;
    if (i < NN) g_dinv[i] = 1.0f / sqrtf(g_deg[i] + 1.0f);
}

__global__ void norm_kernel() {
    int e = blockIdx.x * blockDim.x + threadIdx.x;
    if (e < NE) g_norm[e] = g_dinv[g_src[e]] * g_dinv[g_dst[e]];
}

// ---------------- fp32 tiled GEMM: C[M,NT] = op(A)[M,128] * W[128,NT] --------
// op(A) = relu(A + abias) when RELU, else A.  BM=64, BN=64, BK=16, 256 thr.
template <int NT, bool RELU>
__global__ void gemm_kernel(const float* __restrict__ A,
                            const float* __restrict__ abias,
                            const float* __restrict__ W,
                            float* __restrict__ C, int M) {
    __shared__ float As[16][65];  // [k][row], padded
    __shared__ float Ws[16][64];  // [k][col]

    const int tid = threadIdx.x;
    const int tx = tid & 15;      // output col group
    const int ty = tid >> 4;      // output row group
    const int rowBase = blockIdx.x * 64;
    const int colBase = blockIdx.y * 64;

    const int arow = tid >> 2;         // 0..63
    const int akq  = (tid & 3) * 4;    // 0,4,8,12
    const int wk   = tid >> 4;         // 0..15
    const int wc   = (tid & 15) * 4;   // 0..60

    float acc[4][4];
    #pragma unroll
    for (int i = 0; i < 4; i++)
        #pragma unroll
        for (int j = 0; j < 4; j++) acc[i][j] = 0.0f;

    for (int k0 = 0; k0 < KD; k0 += 16) {
        int gr = rowBase + arow;
        float4 av = make_float4(0.f, 0.f, 0.f, 0.f);
        if (gr < M) av = *(const float4*)(A + (size_t)gr * KD + k0 + akq);
        if (RELU) {
            float4 bb = *(const float4*)(abias + k0 + akq);
            av.x = fmaxf(av.x + bb.x, 0.f);
            av.y = fmaxf(av.y + bb.y, 0.f);
            av.z = fmaxf(av.z + bb.z, 0.f);
            av.w = fmaxf(av.w + bb.w, 0.f);
        }
        As[akq + 0][arow] = av.x;
        As[akq + 1][arow] = av.y;
        As[akq + 2][arow] = av.z;
        As[akq + 3][arow] = av.w;

        *(float4*)&Ws[wk][wc] =
            *(const float4*)(W + (size_t)(k0 + wk) * NT + colBase + wc);
        __syncthreads();

        #pragma unroll
        for (int kk = 0; kk < 16; kk++) {
            float4 b = *(const float4*)&Ws[kk][tx * 4];
            float a[4];
            #pragma unroll
            for (int i = 0; i < 4; i++) a[i] = As[kk][ty * 4 + i];
            #pragma unroll
            for (int i = 0; i < 4; i++) {
                acc[i][0] = fmaf(a[i], b.x, acc[i][0]);
                acc[i][1] = fmaf(a[i], b.y, acc[i][1]);
                acc[i][2] = fmaf(a[i], b.z, acc[i][2]);
                acc[i][3] = fmaf(a[i], b.w, acc[i][3]);
            }
        }
        __syncthreads();
    }

    #pragma unroll
    for (int i = 0; i < 4; i++) {
        int gr = rowBase + ty * 4 + i;
        if (gr < M) {
            *(float4*)(C + (size_t)gr * NT + colBase + tx * 4) =
                make_float4(acc[i][0], acc[i][1], acc[i][2], acc[i][3]);
        }
    }
}

// ---------------- aggregation ------------------------------------------------
// a1[n,:] = h1[n,:] * dinv[n]^2     (self-loop term, also initializes buffer)
__global__ void self_init128(const float* __restrict__ h, float* __restrict__ out) {
    int idx = blockIdx.x * blockDim.x + threadIdx.x;  // over NN*32 float4s
    if (idx >= NN * 32) return;
    int node = idx >> 5;
    float d = g_dinv[node];
    float w = d * d;
    float4 v = ((const float4*)h)[idx];
    v.x *= w; v.y *= w; v.z *= w; v.w *= w;
    ((float4*)out)[idx] = v;
}

// out[n,:] = h2[n,:] * dinv[n]^2 + b2
__global__ void self_init64(const float* __restrict__ h,
                            const float* __restrict__ bias,
                            float* __restrict__ out) {
    int idx = blockIdx.x * blockDim.x + threadIdx.x;  // over NN*16 float4s
    if (idx >= NN * 16) return;
    int node = idx >> 4;
    int q = idx & 15;
    float d = g_dinv[node];
    float w = d * d;
    float4 v = ((const float4*)h)[idx];
    float4 bb = ((const float4*)bias)[q];
    v.x = v.x * w + bb.x;
    v.y = v.y * w + bb.y;
    v.z = v.z * w + bb.z;
    v.w = v.w * w + bb.w;
    ((float4*)out)[idx] = v;
}

// warp per edge, 128 features: out[dst,:] += h[src,:] * norm  (v4 RED)
__global__ void agg_edges128(const float* __restrict__ h, float* __restrict__ out) {
    int t = blockIdx.x * blockDim.x + threadIdx.x;
    int e = t >> 5;
    int lane = t & 31;
    if (e >= NE) return;
    int s = g_src[e];
    int d = g_dst[e];
    float nm = g_norm[e];
    float4 v = ((const float4*)(h + (size_t)s * 128))[lane];
    v.x *= nm; v.y *= nm; v.z *= nm; v.w *= nm;
    red_v4(out + (size_t)d * 128 + lane * 4, v);
}

// half-warp (16 lanes) per edge, 64 features  (v4 RED)
__global__ void agg_edges64(const float* __restrict__ h, float* __restrict__ out) {
    int t = blockIdx.x * blockDim.x + threadIdx.x;
    int e = t >> 4;
    int lane = t & 15;
    if (e >= NE) return;
    int s = g_src[e];
    int d = g_dst[e];
    float nm = g_norm[e];
    float4 v = ((const float4*)(h + (size_t)s * 64))[lane];
    v.x *= nm; v.y *= nm; v.z *= nm; v.w *= nm;
    red_v4(out + (size_t)d * 64 + lane * 4, v);
}

// ---------------- launcher ---------------------------------------------------
extern "C" void kernel_launch(void* const* d_in, const int* in_sizes, int n_in,
                              void* d_out, int out_size) {
    const float* x  = (const float*)d_in[0];
    const void*  ei = d_in[1];
    const float* W1 = (const float*)d_in[2];
    const float* b1 = (const float*)d_in[3];
    const float* W2 = (const float*)d_in[4];
    const float* b2 = (const float*)d_in[5];
    float* out = (float*)d_out;

    float* h1 = nullptr; float* a1 = nullptr; float* h2 = nullptr;
    cudaGetSymbolAddress((void**)&h1, g_h1);
    cudaGetSymbolAddress((void**)&a1, g_a1);
    cudaGetSymbolAddress((void**)&h2, g_h2);

    const int T = 256;
    // 1. edge preprocessing
    detect_kernel<<<1, 64>>>(ei);
    convert_edges<<<(NE + T - 1) / T, T>>>(ei);
    zero_deg_kernel<<<(NN + T - 1) / T, T>>>();
    deg_accum_kernel<<<(NE + T - 1) / T, T>>>();
    dinv_kernel<<<(NN + T - 1) / T, T>>>();
    norm_kernel<<<(NE + T - 1) / T, T>>>();

    // 2. layer 1: h1 = x @ W1, aggregate into a1
    {
        dim3 grid((NN + 63) / 64, HID / 64);
        gemm_kernel<HID, false><<<grid, 256>>>(x, nullptr, W1, h1, NN);
    }
    self_init128<<<(NN * 32 + T - 1) / T, T>>>(h1, a1);
    agg_edges128<<<(NE * 32 + T - 1) / T, T>>>(h1, a1);

    // 3. layer 2: h2 = relu(a1 + b1) @ W2, aggregate into out (+b2)
    {
        dim3 grid((NN + 63) / 64, FO / 64);
        gemm_kernel<FO, true><<<grid, 256>>>(a1, b1, W2, h2, NN);
    }
    self_init64<<<(NN * 16 + T - 1) / T, T>>>(h2, b2, out);
    agg_edges64<<<(NE * 32 + T - 1) / T, T>>>(h2, out);
}

// round 12
// speedup vs baseline: 1.6855x; 1.1826x over previous
#include <cuda_runtime.h>
#include <cuda_bf16.h>
#include <cstdint>

// Problem constants (fixed by the dataset)
static constexpr int NN  = 100000;   // nodes
static constexpr int NE  = 600000;   // edges

// ---------------- scratch (device globals: no allocations allowed) ----------
__device__ int   g_is64;
__device__ int   g_src[NE];
__device__ int   g_dst[NE];
__device__ float g_deg[NN];
__device__ float g_dinv[NN];
__device__ float g_norm[NE];
__device__ float g_h1[(size_t)NN * 128];   // x @ W1 (raw)
__device__ float g_a1[(size_t)NN * 128];   // aggregated layer-1
__device__ float g_h2[(size_t)NN * 64];    // relu(a1+b1) @ W2 (raw)
__device__ __nv_bfloat16 g_w1h[128 * 128]; // [n][k] transposed, hi
__device__ __nv_bfloat16 g_w1l[128 * 128];
__device__ __nv_bfloat16 g_w2h[64 * 128];
__device__ __nv_bfloat16 g_w2l[64 * 128];

// ---------------- helpers ----------------------------------------------------
__device__ __forceinline__ uint32_t smem_to_u32(const void* p) {
    uint32_t a;
    asm("{ .reg .u64 t; cvta.to.shared.u64 t, %1; cvt.u32.u64 %0, t; }"
        : "=r"(a) : "l"(p));
    return a;
}
// XOR-swizzle a byte offset within a [rows][256B] tile (16B chunks x row%8)
__device__ __forceinline__ int swz(int o) { return o ^ ((o >> 4) & 0x70); }

__device__ __forceinline__ void ldm_x4(uint32_t* r, uint32_t addr) {
    asm volatile("ldmatrix.sync.aligned.m8n8.x4.shared.b16 {%0,%1,%2,%3}, [%4];"
                 : "=r"(r[0]), "=r"(r[1]), "=r"(r[2]), "=r"(r[3]) : "r"(addr));
}
__device__ __forceinline__ void ldm_x2(uint32_t* r, uint32_t addr) {
    asm volatile("ldmatrix.sync.aligned.m8n8.x2.shared.b16 {%0,%1}, [%2];"
                 : "=r"(r[0]), "=r"(r[1]) : "r"(addr));
}
__device__ __forceinline__ void mma_bf16(float* c, const uint32_t* a, const uint32_t* b) {
    asm volatile(
        "mma.sync.aligned.m16n8k16.row.col.f32.bf16.bf16.f32 "
        "{%0,%1,%2,%3}, {%4,%5,%6,%7}, {%8,%9}, {%0,%1,%2,%3};"
        : "+f"(c[0]), "+f"(c[1]), "+f"(c[2]), "+f"(c[3])
        : "r"(a[0]), "r"(a[1]), "r"(a[2]), "r"(a[3]), "r"(b[0]), "r"(b[1]));
}

__device__ __forceinline__ void red_v4(float* addr, float4 v) {
    asm volatile("red.global.add.v4.f32 [%0], {%1, %2, %3, %4};"
                 :: "l"(addr), "f"(v.x), "f"(v.y), "f"(v.z), "f"(v.w)
                 : "memory");
}

__device__ __forceinline__ uint32_t pack_bf2(__nv_bfloat16 a, __nv_bfloat16 b) {
    __nv_bfloat162 t = __halves2bfloat162(a, b);
    return *reinterpret_cast<uint32_t*>(&t);
}
__device__ __forceinline__ void split1(float v, __nv_bfloat16& h, __nv_bfloat16& l) {
    h = __float2bfloat16(v);
    l = __float2bfloat16(v - __bfloat162float(h));
}

// ---------------- edge preprocessing -----------------------------------------
__global__ void detect_kernel(const void* ei) {
    const int* p = (const int*)ei;
    bool z = (p[2 * threadIdx.x + 1] == 0);
    unsigned m = __ballot_sync(0xffffffffu, z);
    __shared__ int ok[2];
    if ((threadIdx.x & 31) == 0) ok[threadIdx.x >> 5] = (m == 0xffffffffu) ? 1 : 0;
    __syncthreads();
    if (threadIdx.x == 0) g_is64 = ok[0] & ok[1];
}

__global__ void convert_edges(const void* ei) {
    int e = blockIdx.x * blockDim.x + threadIdx.x;
    if (e >= NE) return;
    if (g_is64) {
        const long long* p = (const long long*)ei;
        g_src[e] = (int)p[e];
        g_dst[e] = (int)p[e + NE];
    } else {
        const int* p = (const int*)ei;
        g_src[e] = p[e];
        g_dst[e] = p[e + NE];
    }
}

__global__ void zero_deg_kernel() {
    int i = blockIdx.x * blockDim.x + threadIdx.x;
    if (i < NN) g_deg[i] = 0.0f;
}
__global__ void deg_accum_kernel() {
    int e = blockIdx.x * blockDim.x + threadIdx.x;
    if (e < NE) atomicAdd(&g_deg[g_dst[e]], 1.0f);
}
__global__ void dinv_kernel() {
    int i = blockIdx.x * blockDim.x + threadIdx.x;
    if (i < NN) g_dinv[i] = 1.0f / sqrtf(g_deg[i] + 1.0f);
}
__global__ void norm_kernel() {
    int e = blockIdx.x * blockDim.x + threadIdx.x;
    if (e < NE) g_norm[e] = g_dinv[g_src[e]] * g_dinv[g_dst[e]];
}

// W [K=128][Ncols] row-major -> out[n][k] (transposed), split hi/lo (tiny)
__global__ void wconv_kernel(const float* __restrict__ W, int Ncols,
                             __nv_bfloat16* __restrict__ oh, __nv_bfloat16* __restrict__ ol) {
    int i = blockIdx.x * blockDim.x + threadIdx.x;
    if (i >= 128 * Ncols) return;
    int k = i / Ncols, n = i % Ncols;
    __nv_bfloat16 h, l;
    split1(W[i], h, l);
    oh[n * 128 + k] = h;
    ol[n * 128 + k] = l;
}

// ---------------- HMMA GEMM with in-kernel hi/lo split -----------------------
// C[M,NDIM] = op(A)[M,128] @ W[128,NDIM];  op(A) = relu(A + abias) when RELU.
// A fp32 row-major; B pre-split bf16 [NDIM][128] hi/lo.
// 3 passes: Ah*Bh + Ah*Bl + Al*Bh, fp32 accum.
// Epilogue: C raw; Cs = C * dinv[row]^2 (+ cbias when CBIAS).
template <int NDIM, bool RELU, bool CBIAS>
__global__ void __launch_bounds__(256)
mma_gemm(const float* __restrict__ A, const float* __restrict__ abias,
         const __nv_bfloat16* __restrict__ Bh, const __nv_bfloat16* __restrict__ Bl,
         float* __restrict__ C, float* __restrict__ Cs,
         const float* __restrict__ cbias, int M) {
    extern __shared__ char smem[];
    constexpr int WARP_N = NDIM / 2;   // 64 or 32
    constexpr int NT_N = WARP_N / 8;   // 8 or 4
    constexpr int A_BYTES = 128 * 256; // one bf16 tile: 128 rows x 256B
    constexpr int B_BYTES = NDIM * 256;

    const uint32_t sAh = smem_to_u32(smem);
    const uint32_t sAl = sAh + A_BYTES;
    const uint32_t sB0 = sAl + A_BYTES;
    const uint32_t sB1 = sB0 + B_BYTES;

    const int tid = threadIdx.x, wid = tid >> 5, lane = tid & 31;
    const int warp_row = wid & 3, warp_col = wid >> 2;
    const int rowBase = blockIdx.x * 128;
    const int vr = (M - rowBase < 128) ? (M - rowBase) : 128;

    // ---- A loader: fp32 -> bf16 hi/lo, swizzled SMEM (no extra gmem traffic)
    {
        const float* gA = A + (size_t)rowBase * 128;
        for (int idx = tid; idx < 128 * 16; idx += 256) {
            int row = idx >> 4, c = idx & 15;          // c: 8-float chunk
            float4 v0 = make_float4(0.f, 0.f, 0.f, 0.f);
            float4 v1 = v0;
            if (row < vr) {
                v0 = *(const float4*)(gA + (size_t)row * 128 + c * 8);
                v1 = *(const float4*)(gA + (size_t)row * 128 + c * 8 + 4);
            }
            if (RELU) {
                float4 b0 = *(const float4*)(abias + c * 8);
                float4 b1 = *(const float4*)(abias + c * 8 + 4);
                v0.x = fmaxf(v0.x + b0.x, 0.f); v0.y = fmaxf(v0.y + b0.y, 0.f);
                v0.z = fmaxf(v0.z + b0.z, 0.f); v0.w = fmaxf(v0.w + b0.w, 0.f);
                v1.x = fmaxf(v1.x + b1.x, 0.f); v1.y = fmaxf(v1.y + b1.y, 0.f);
                v1.z = fmaxf(v1.z + b1.z, 0.f); v1.w = fmaxf(v1.w + b1.w, 0.f);
            }
            __nv_bfloat16 h[8], l[8];
            split1(v0.x, h[0], l[0]); split1(v0.y, h[1], l[1]);
            split1(v0.z, h[2], l[2]); split1(v0.w, h[3], l[3]);
            split1(v1.x, h[4], l[4]); split1(v1.y, h[5], l[5]);
            split1(v1.z, h[6], l[6]); split1(v1.w, h[7], l[7]);
            int o = swz(row * 256 + c * 16);
            *(uint4*)(smem + o) = make_uint4(
                pack_bf2(h[0], h[1]), pack_bf2(h[2], h[3]),
                pack_bf2(h[4], h[5]), pack_bf2(h[6], h[7]));
            *(uint4*)(smem + A_BYTES + o) = make_uint4(
                pack_bf2(l[0], l[1]), pack_bf2(l[2], l[3]),
                pack_bf2(l[4], l[5]), pack_bf2(l[6], l[7]));
        }
    }
    // ---- B loader: pre-split bf16 -> swizzled SMEM
    {
        for (int idx = tid; idx < NDIM * 16; idx += 256) {
            int row = idx >> 4, c = idx & 15;
            int o = swz(row * 256 + c * 16);
            *(uint4*)(smem + 2 * A_BYTES + o) =
                *(const uint4*)(Bh + (size_t)row * 128 + c * 8);
            *(uint4*)(smem + 2 * A_BYTES + B_BYTES + o) =
                *(const uint4*)(Bl + (size_t)row * 128 + c * 8);
        }
    }
    __syncthreads();

    float acc[2][NT_N][4];
    #pragma unroll
    for (int i = 0; i < 2; i++)
        #pragma unroll
        for (int j = 0; j < NT_N; j++)
            #pragma unroll
            for (int q = 0; q < 4; q++) acc[i][j][q] = 0.0f;

    // per-lane ldmatrix addressing constants
    const int at = lane >> 3;
    const int ar = lane & 7;
    const int aRow0 = warp_row * 32 + ar + (at & 1) * 8;  // + mi*16
    const int aKt = (at >> 1) * 8;
    const int l15 = lane & 15;
    const int bt = l15 >> 3, br = l15 & 7;
    const int bN0 = warp_col * WARP_N + br;               // + ni*8
    const int bKt = bt * 8;

    auto run_pass = [&](uint32_t aBase, uint32_t bBase) {
        #pragma unroll
        for (int ks = 0; ks < 8; ks++) {
            uint32_t a[2][4];
            #pragma unroll
            for (int mi = 0; mi < 2; mi++) {
                int row = aRow0 + mi * 16;
                ldm_x4(a[mi], aBase + swz(row * 256 + (ks * 16 + aKt) * 2));
            }
            uint32_t b[NT_N][2];
            #pragma unroll
            for (int ni = 0; ni < NT_N; ni++) {
                int n = bN0 + ni * 8;
                ldm_x2(b[ni], bBase + swz(n * 256 + (ks * 16 + bKt) * 2));
            }
            #pragma unroll
            for (int mi = 0; mi < 2; mi++)
                #pragma unroll
                for (int ni = 0; ni < NT_N; ni++)
                    mma_bf16(acc[mi][ni], a[mi], b[ni]);
        }
    };

    run_pass(sAh, sB0);   // Ah * Bh
    run_pass(sAh, sB1);   // Ah * Bl
    run_pass(sAl, sB0);   // Al * Bh

    // ---- epilogue: raw C and scaled Cs (fused self-loop init)
    const int erow0 = rowBase + warp_row * 32 + (lane >> 2);
    const int ecol0 = warp_col * WARP_N + (lane & 3) * 2;
    #pragma unroll
    for (int mi = 0; mi < 2; mi++) {
        #pragma unroll
        for (int p = 0; p < 2; p++) {
            int row = erow0 + mi * 16 + p * 8;
            if (row >= M) continue;
            float d = g_dinv[row];
            float w = d * d;
            #pragma unroll
            for (int ni = 0; ni < NT_N; ni++) {
                int col = ecol0 + ni * 8;
                float2 v = make_float2(acc[mi][ni][2 * p], acc[mi][ni][2 * p + 1]);
                *(float2*)(C + (size_t)row * NDIM + col) = v;
                float2 s;
                if (CBIAS) {
                    s.x = v.x * w + __ldg(cbias + col);
                    s.y = v.y * w + __ldg(cbias + col + 1);
                } else {
                    s.x = v.x * w;
                    s.y = v.y * w;
                }
                *(float2*)(Cs + (size_t)row * NDIM + col) = s;
            }
        }
    }
}

// ---------------- edge aggregation (vectorized RED) --------------------------
__global__ void agg_edges128(const float* __restrict__ h, float* __restrict__ out) {
    int t = blockIdx.x * blockDim.x + threadIdx.x;
    int e = t >> 5;
    int lane = t & 31;
    if (e >= NE) return;
    int s = g_src[e];
    int d = g_dst[e];
    float nm = g_norm[e];
    float4 v = ((const float4*)(h + (size_t)s * 128))[lane];
    v.x *= nm; v.y *= nm; v.z *= nm; v.w *= nm;
    red_v4(out + (size_t)d * 128 + lane * 4, v);
}

__global__ void agg_edges64(const float* __restrict__ h, float* __restrict__ out) {
    int t = blockIdx.x * blockDim.x + threadIdx.x;
    int e = t >> 4;
    int lane = t & 15;
    if (e >= NE) return;
    int s = g_src[e];
    int d = g_dst[e];
    float nm = g_norm[e];
    float4 v = ((const float4*)(h + (size_t)s * 64))[lane];
    v.x *= nm; v.y *= nm; v.z *= nm; v.w *= nm;
    red_v4(out + (size_t)d * 64 + lane * 4, v);
}

// ---------------- launcher ---------------------------------------------------
extern "C" void kernel_launch(void* const* d_in, const int* in_sizes, int n_in,
                              void* d_out, int out_size) {
    const float* x  = (const float*)d_in[0];
    const void*  ei = d_in[1];
    const float* W1 = (const float*)d_in[2];
    const float* b1 = (const float*)d_in[3];
    const float* W2 = (const float*)d_in[4];
    const float* b2 = (const float*)d_in[5];
    float* out = (float*)d_out;

    float *h1, *a1, *h2;
    __nv_bfloat16 *w1h, *w1l, *w2h, *w2l;
    cudaGetSymbolAddress((void**)&h1, g_h1);
    cudaGetSymbolAddress((void**)&a1, g_a1);
    cudaGetSymbolAddress((void**)&h2, g_h2);
    cudaGetSymbolAddress((void**)&w1h, g_w1h);
    cudaGetSymbolAddress((void**)&w1l, g_w1l);
    cudaGetSymbolAddress((void**)&w2h, g_w2h);
    cudaGetSymbolAddress((void**)&w2l, g_w2l);

    constexpr int SMEM1 = 2 * 128 * 256 + 2 * 128 * 256;  // Ah+Al+Bh+Bl = 131072
    constexpr int SMEM2 = 2 * 128 * 256 + 2 * 64 * 256;   // 98304
    cudaFuncSetAttribute(mma_gemm<128, false, false>,
                         cudaFuncAttributeMaxDynamicSharedMemorySize, SMEM1);
    cudaFuncSetAttribute(mma_gemm<64, true, true>,
                         cudaFuncAttributeMaxDynamicSharedMemorySize, SMEM2);

    const int T = 256;
    // 1. edge preprocessing
    detect_kernel<<<1, 64>>>(ei);
    convert_edges<<<(NE + T - 1) / T, T>>>(ei);
    zero_deg_kernel<<<(NN + T - 1) / T, T>>>();
    deg_accum_kernel<<<(NE + T - 1) / T, T>>>();
    dinv_kernel<<<(NN + T - 1) / T, T>>>();
    norm_kernel<<<(NE + T - 1) / T, T>>>();

    // 2. weight splits (tiny)
    wconv_kernel<<<(128 * 128 + T - 1) / T, T>>>(W1, 128, w1h, w1l);
    wconv_kernel<<<(128 * 64 + T - 1) / T, T>>>(W2, 64, w2h, w2l);

    // 3. layer 1: h1 = x @ W1; epilogue writes a1 = h1*dinv^2; then edges
    const int GRID = (NN + 127) / 128;  // 782
    mma_gemm<128, false, false><<<GRID, 256, SMEM1>>>(x, nullptr, w1h, w1l,
                                                      h1, a1, nullptr, NN);
    agg_edges128<<<(NE * 32 + T - 1) / T, T>>>(h1, a1);

    // 4. layer 2: h2 = relu(a1+b1) @ W2; epilogue writes out = h2*dinv^2 + b2
    mma_gemm<64, true, true><<<GRID, 256, SMEM2>>>(a1, b1, w2h, w2l,
                                                   h2, out, b2, NN);
    agg_edges64<<<(NE * 16 + T - 1) / T, T>>>(h2, out);
}

// round 13
// speedup vs baseline: 2.0825x; 1.2355x over previous
#include <cuda_runtime.h>
#include <cuda_bf16.h>
#include <cstdint>

// Problem constants (fixed by the dataset)
static constexpr int NN  = 100000;   // nodes
static constexpr int NE  = 600000;   // edges
static constexpr int NBLK = (NN + 1023) / 1024;  // 98 scan blocks

// ---------------- scratch (device globals: no allocations allowed) ----------
__device__ int   g_is64;
__device__ int   g_src[NE];
__device__ int   g_dst[NE];
__device__ int   g_cnt[NN];      // in-degree (excl self)
__device__ int   g_rowptr[NN];   // CSR row starts
__device__ int   g_fill[NN];     // scatter fill counters
__device__ int   g_bsum[NBLK];
__device__ int   g_boff[NBLK];
__device__ float g_dinv[NN];
__device__ int   g_csrc[NE];     // CSR-sorted source ids
__device__ float g_cnorm[NE];    // CSR-sorted edge norms
__device__ float g_h1[(size_t)NN * 128];   // x @ W1 (raw)
__device__ float g_a1[(size_t)NN * 128];   // aggregated layer-1
__device__ float g_h2[(size_t)NN * 64];    // relu(a1+b1) @ W2 (raw)
__device__ __nv_bfloat16 g_w1h[128 * 128]; // [n][k] transposed, hi
__device__ __nv_bfloat16 g_w1l[128 * 128];
__device__ __nv_bfloat16 g_w2h[64 * 128];
__device__ __nv_bfloat16 g_w2l[64 * 128];

// ---------------- helpers ----------------------------------------------------
__device__ __forceinline__ uint32_t smem_to_u32(const void* p) {
    uint32_t a;
    asm("{ .reg .u64 t; cvta.to.shared.u64 t, %1; cvt.u32.u64 %0, t; }"
        : "=r"(a) : "l"(p));
    return a;
}
// XOR-swizzle a byte offset within a [rows][256B] tile (16B chunks x row%8)
__device__ __forceinline__ int swz(int o) { return o ^ ((o >> 4) & 0x70); }

__device__ __forceinline__ void ldm_x4(uint32_t* r, uint32_t addr) {
    asm volatile("ldmatrix.sync.aligned.m8n8.x4.shared.b16 {%0,%1,%2,%3}, [%4];"
                 : "=r"(r[0]), "=r"(r[1]), "=r"(r[2]), "=r"(r[3]) : "r"(addr));
}
__device__ __forceinline__ void ldm_x2(uint32_t* r, uint32_t addr) {
    asm volatile("ldmatrix.sync.aligned.m8n8.x2.shared.b16 {%0,%1}, [%2];"
                 : "=r"(r[0]), "=r"(r[1]) : "r"(addr));
}
__device__ __forceinline__ void mma_bf16(float* c, const uint32_t* a, const uint32_t* b) {
    asm volatile(
        "mma.sync.aligned.m16n8k16.row.col.f32.bf16.bf16.f32 "
        "{%0,%1,%2,%3}, {%4,%5,%6,%7}, {%8,%9}, {%0,%1,%2,%3};"
        : "+f"(c[0]), "+f"(c[1]), "+f"(c[2]), "+f"(c[3])
        : "r"(a[0]), "r"(a[1]), "r"(a[2]), "r"(a[3]), "r"(b[0]), "r"(b[1]));
}

__device__ __forceinline__ uint32_t pack_bf2(__nv_bfloat16 a, __nv_bfloat16 b) {
    __nv_bfloat162 t = __halves2bfloat162(a, b);
    return *reinterpret_cast<uint32_t*>(&t);
}
__device__ __forceinline__ void split1(float v, __nv_bfloat16& h, __nv_bfloat16& l) {
    h = __float2bfloat16(v);
    l = __float2bfloat16(v - __bfloat162float(h));
}

// ---------------- edge preprocessing -----------------------------------------
__global__ void zero_cnt_kernel() {
    int i = blockIdx.x * blockDim.x + threadIdx.x;
    if (i < NN) g_cnt[i] = 0;
}

__global__ void detect_kernel(const void* ei) {
    const int* p = (const int*)ei;
    bool z = (p[2 * threadIdx.x + 1] == 0);
    unsigned m = __ballot_sync(0xffffffffu, z);
    __shared__ int ok[2];
    if ((threadIdx.x & 31) == 0) ok[threadIdx.x >> 5] = (m == 0xffffffffu) ? 1 : 0;
    __syncthreads();
    if (threadIdx.x == 0) g_is64 = ok[0] & ok[1];
}

// convert + in-degree count fused
__global__ void convert_count_kernel(const void* ei) {
    int e = blockIdx.x * blockDim.x + threadIdx.x;
    if (e >= NE) return;
    int s, d;
    if (g_is64) {
        const long long* p = (const long long*)ei;
        s = (int)p[e];
        d = (int)p[e + NE];
    } else {
        const int* p = (const int*)ei;
        s = p[e];
        d = p[e + NE];
    }
    g_src[e] = s;
    g_dst[e] = d;
    atomicAdd(&g_cnt[d], 1);
}

__global__ void dinv_kernel() {
    int i = blockIdx.x * blockDim.x + threadIdx.x;
    if (i < NN) g_dinv[i] = rsqrtf((float)g_cnt[i] + 1.0f);
}

// ---------------- CSR build: 3-kernel exclusive scan + scatter ---------------
__global__ void scan1_kernel() {  // grid NBLK, block 1024
    __shared__ int sh[1024];
    int b = blockIdx.x, t = threadIdx.x;
    int i = b * 1024 + t;
    int v = (i < NN) ? g_cnt[i] : 0;
    sh[t] = v;
    __syncthreads();
    #pragma unroll
    for (int off = 1; off < 1024; off <<= 1) {
        int x = (t >= off) ? sh[t - off] : 0;
        __syncthreads();
        sh[t] += x;
        __syncthreads();
    }
    if (i < NN) g_rowptr[i] = sh[t] - v;   // exclusive within block
    if (t == 1023) g_bsum[b] = sh[1023];
}

__global__ void scan2_kernel() {  // 1 block, 128 threads
    __shared__ int sh[NBLK];
    int t = threadIdx.x;
    if (t < NBLK) sh[t] = g_bsum[t];
    __syncthreads();
    if (t == 0) {
        int run = 0;
        for (int j = 0; j < NBLK; j++) { int x = sh[j]; sh[j] = run; run += x; }
    }
    __syncthreads();
    if (t < NBLK) g_boff[t] = sh[t];
}

__global__ void scan3_kernel() {
    int i = blockIdx.x * blockDim.x + threadIdx.x;
    if (i < NN) {
        g_rowptr[i] += g_boff[i >> 10];
        g_fill[i] = 0;
    }
}

__global__ void scatter_kernel() {
    int e = blockIdx.x * blockDim.x + threadIdx.x;
    if (e >= NE) return;
    int s = g_src[e], d = g_dst[e];
    int pos = g_rowptr[d] + atomicAdd(&g_fill[d], 1);
    g_csrc[pos] = s;
    g_cnorm[pos] = g_dinv[s] * g_dinv[d];
}

// W [K=128][Ncols] row-major -> out[n][k] (transposed), split hi/lo (tiny)
__global__ void wconv_kernel(const float* __restrict__ W, int Ncols,
                             __nv_bfloat16* __restrict__ oh, __nv_bfloat16* __restrict__ ol) {
    int i = blockIdx.x * blockDim.x + threadIdx.x;
    if (i >= 128 * Ncols) return;
    int k = i / Ncols, n = i % Ncols;
    __nv_bfloat16 h, l;
    split1(W[i], h, l);
    oh[n * 128 + k] = h;
    ol[n * 128 + k] = l;
}

// ---------------- HMMA GEMM with in-kernel hi/lo split -----------------------
// C[M,NDIM] = op(A)[M,128] @ W[128,NDIM];  op(A) = relu(A + abias) when RELU.
// 3 passes: Ah*Bh + Ah*Bl + Al*Bh, fp32 accum. Epilogue: raw C only.
template <int NDIM, bool RELU>
__global__ void __launch_bounds__(256)
mma_gemm(const float* __restrict__ A, const float* __restrict__ abias,
         const __nv_bfloat16* __restrict__ Bh, const __nv_bfloat16* __restrict__ Bl,
         float* __restrict__ C, int M) {
    extern __shared__ char smem[];
    constexpr int WARP_N = NDIM / 2;   // 64 or 32
    constexpr int NT_N = WARP_N / 8;   // 8 or 4
    constexpr int A_BYTES = 128 * 256;
    constexpr int B_BYTES = NDIM * 256;

    const uint32_t sAh = smem_to_u32(smem);
    const uint32_t sAl = sAh + A_BYTES;
    const uint32_t sB0 = sAl + A_BYTES;
    const uint32_t sB1 = sB0 + B_BYTES;

    const int tid = threadIdx.x, wid = tid >> 5, lane = tid & 31;
    const int warp_row = wid & 3, warp_col = wid >> 2;
    const int rowBase = blockIdx.x * 128;
    const int vr = (M - rowBase < 128) ? (M - rowBase) : 128;

    // ---- A loader: fp32 -> bf16 hi/lo, swizzled SMEM
    {
        const float* gA = A + (size_t)rowBase * 128;
        for (int idx = tid; idx < 128 * 16; idx += 256) {
            int row = idx >> 4, c = idx & 15;
            float4 v0 = make_float4(0.f, 0.f, 0.f, 0.f);
            float4 v1 = v0;
            if (row < vr) {
                v0 = *(const float4*)(gA + (size_t)row * 128 + c * 8);
                v1 = *(const float4*)(gA + (size_t)row * 128 + c * 8 + 4);
            }
            if (RELU) {
                float4 b0 = *(const float4*)(abias + c * 8);
                float4 b1 = *(const float4*)(abias + c * 8 + 4);
                v0.x = fmaxf(v0.x + b0.x, 0.f); v0.y = fmaxf(v0.y + b0.y, 0.f);
                v0.z = fmaxf(v0.z + b0.z, 0.f); v0.w = fmaxf(v0.w + b0.w, 0.f);
                v1.x = fmaxf(v1.x + b1.x, 0.f); v1.y = fmaxf(v1.y + b1.y, 0.f);
                v1.z = fmaxf(v1.z + b1.z, 0.f); v1.w = fmaxf(v1.w + b1.w, 0.f);
            }
            __nv_bfloat16 h[8], l[8];
            split1(v0.x, h[0], l[0]); split1(v0.y, h[1], l[1]);
            split1(v0.z, h[2], l[2]); split1(v0.w, h[3], l[3]);
            split1(v1.x, h[4], l[4]); split1(v1.y, h[5], l[5]);
            split1(v1.z, h[6], l[6]); split1(v1.w, h[7], l[7]);
            int o = swz(row * 256 + c * 16);
            *(uint4*)(smem + o) = make_uint4(
                pack_bf2(h[0], h[1]), pack_bf2(h[2], h[3]),
                pack_bf2(h[4], h[5]), pack_bf2(h[6], h[7]));
            *(uint4*)(smem + A_BYTES + o) = make_uint4(
                pack_bf2(l[0], l[1]), pack_bf2(l[2], l[3]),
                pack_bf2(l[4], l[5]), pack_bf2(l[6], l[7]));
        }
    }
    // ---- B loader
    {
        for (int idx = tid; idx < NDIM * 16; idx += 256) {
            int row = idx >> 4, c = idx & 15;
            int o = swz(row * 256 + c * 16);
            *(uint4*)(smem + 2 * A_BYTES + o) =
                *(const uint4*)(Bh + (size_t)row * 128 + c * 8);
            *(uint4*)(smem + 2 * A_BYTES + B_BYTES + o) =
                *(const uint4*)(Bl + (size_t)row * 128 + c * 8);
        }
    }
    __syncthreads();

    float acc[2][NT_N][4];
    #pragma unroll
    for (int i = 0; i < 2; i++)
        #pragma unroll
        for (int j = 0; j < NT_N; j++)
            #pragma unroll
            for (int q = 0; q < 4; q++) acc[i][j][q] = 0.0f;

    const int at = lane >> 3;
    const int ar = lane & 7;
    const int aRow0 = warp_row * 32 + ar + (at & 1) * 8;
    const int aKt = (at >> 1) * 8;
    const int l15 = lane & 15;
    const int bt = l15 >> 3, br = l15 & 7;
    const int bN0 = warp_col * WARP_N + br;
    const int bKt = bt * 8;

    auto run_pass = [&](uint32_t aBase, uint32_t bBase) {
        #pragma unroll
        for (int ks = 0; ks < 8; ks++) {
            uint32_t a[2][4];
            #pragma unroll
            for (int mi = 0; mi < 2; mi++) {
                int row = aRow0 + mi * 16;
                ldm_x4(a[mi], aBase + swz(row * 256 + (ks * 16 + aKt) * 2));
            }
            uint32_t b[NT_N][2];
            #pragma unroll
            for (int ni = 0; ni < NT_N; ni++) {
                int n = bN0 + ni * 8;
                ldm_x2(b[ni], bBase + swz(n * 256 + (ks * 16 + bKt) * 2));
            }
            #pragma unroll
            for (int mi = 0; mi < 2; mi++)
                #pragma unroll
                for (int ni = 0; ni < NT_N; ni++)
                    mma_bf16(acc[mi][ni], a[mi], b[ni]);
        }
    };

    run_pass(sAh, sB0);   // Ah * Bh
    run_pass(sAh, sB1);   // Ah * Bl
    run_pass(sAl, sB0);   // Al * Bh

    // ---- epilogue: raw C only
    const int erow0 = rowBase + warp_row * 32 + (lane >> 2);
    const int ecol0 = warp_col * WARP_N + (lane & 3) * 2;
    #pragma unroll
    for (int mi = 0; mi < 2; mi++) {
        #pragma unroll
        for (int p = 0; p < 2; p++) {
            int row = erow0 + mi * 16 + p * 8;
            if (row >= M) continue;
            #pragma unroll
            for (int ni = 0; ni < NT_N; ni++) {
                int col = ecol0 + ni * 8;
                *(float2*)(C + (size_t)row * NDIM + col) =
                    make_float2(acc[mi][ni][2 * p], acc[mi][ni][2 * p + 1]);
            }
        }
    }
}

// ---------------- CSR aggregation (gather-only, no atomics) ------------------
// warp per node, 128 features: out[n,:] = h[n,:]*dinv^2 + sum_e h[src_e,:]*norm_e
__global__ void agg_csr128(const float* __restrict__ h, float* __restrict__ out) {
    int t = blockIdx.x * blockDim.x + threadIdx.x;
    int n = t >> 5;
    int lane = t & 31;
    if (n >= NN) return;
    float dv = g_dinv[n];
    float w = dv * dv;
    const float4* hv = (const float4*)h;
    float4 acc = hv[(size_t)n * 32 + lane];
    acc.x *= w; acc.y *= w; acc.z *= w; acc.w *= w;
    int p = g_rowptr[n];
    int end = p + g_cnt[n];
    for (; p < end; p++) {
        int s = __ldg(&g_csrc[p]);
        float nm = __ldg(&g_cnorm[p]);
        float4 v = hv[(size_t)s * 32 + lane];
        acc.x += v.x * nm; acc.y += v.y * nm;
        acc.z += v.z * nm; acc.w += v.w * nm;
    }
    ((float4*)out)[(size_t)n * 32 + lane] = acc;
}

// half-warp per node, 64 features; adds bias
__global__ void agg_csr64(const float* __restrict__ h,
                          const float* __restrict__ bias,
                          float* __restrict__ out) {
    int t = blockIdx.x * blockDim.x + threadIdx.x;
    int n = t >> 4;
    int lane = t & 15;
    if (n >= NN) return;
    float dv = g_dinv[n];
    float w = dv * dv;
    const float4* hv = (const float4*)h;
    float4 bb = ((const float4*)bias)[lane];
    float4 acc = hv[(size_t)n * 16 + lane];
    acc.x = acc.x * w + bb.x; acc.y = acc.y * w + bb.y;
    acc.z = acc.z * w + bb.z; acc.w = acc.w * w + bb.w;
    int p = g_rowptr[n];
    int end = p + g_cnt[n];
    for (; p < end; p++) {
        int s = __ldg(&g_csrc[p]);
        float nm = __ldg(&g_cnorm[p]);
        float4 v = hv[(size_t)s * 16 + lane];
        acc.x += v.x * nm; acc.y += v.y * nm;
        acc.z += v.z * nm; acc.w += v.w * nm;
    }
    ((float4*)out)[(size_t)n * 16 + lane] = acc;
}

// ---------------- launcher ---------------------------------------------------
extern "C" void kernel_launch(void* const* d_in, const int* in_sizes, int n_in,
                              void* d_out, int out_size) {
    const float* x  = (const float*)d_in[0];
    const void*  ei = d_in[1];
    const float* W1 = (const float*)d_in[2];
    const float* b1 = (const float*)d_in[3];
    const float* W2 = (const float*)d_in[4];
    const float* b2 = (const float*)d_in[5];
    float* out = (float*)d_out;

    float *h1, *a1, *h2;
    __nv_bfloat16 *w1h, *w1l, *w2h, *w2l;
    cudaGetSymbolAddress((void**)&h1, g_h1);
    cudaGetSymbolAddress((void**)&a1, g_a1);
    cudaGetSymbolAddress((void**)&h2, g_h2);
    cudaGetSymbolAddress((void**)&w1h, g_w1h);
    cudaGetSymbolAddress((void**)&w1l, g_w1l);
    cudaGetSymbolAddress((void**)&w2h, g_w2h);
    cudaGetSymbolAddress((void**)&w2l, g_w2l);

    constexpr int SMEM1 = 2 * 128 * 256 + 2 * 128 * 256;  // 131072
    constexpr int SMEM2 = 2 * 128 * 256 + 2 * 64 * 256;   // 98304
    cudaFuncSetAttribute(mma_gemm<128, false>,
                         cudaFuncAttributeMaxDynamicSharedMemorySize, SMEM1);
    cudaFuncSetAttribute(mma_gemm<64, true>,
                         cudaFuncAttributeMaxDynamicSharedMemorySize, SMEM2);

    const int T = 256;
    // 1. edge preprocessing + CSR build
    zero_cnt_kernel<<<(NN + T - 1) / T, T>>>();
    detect_kernel<<<1, 64>>>(ei);
    convert_count_kernel<<<(NE + T - 1) / T, T>>>(ei);
    dinv_kernel<<<(NN + T - 1) / T, T>>>();
    scan1_kernel<<<NBLK, 1024>>>();
    scan2_kernel<<<1, 128>>>();
    scan3_kernel<<<(NN + T - 1) / T, T>>>();
    scatter_kernel<<<(NE + T - 1) / T, T>>>();

    // 2. weight splits (tiny)
    wconv_kernel<<<(128 * 128 + T - 1) / T, T>>>(W1, 128, w1h, w1l);
    wconv_kernel<<<(128 * 64 + T - 1) / T, T>>>(W2, 64, w2h, w2l);

    // 3. layer 1: h1 = x @ W1; CSR aggregate (self + edges) -> a1
    const int GRID = (NN + 127) / 128;  // 782
    mma_gemm<128, false><<<GRID, 256, SMEM1>>>(x, nullptr, w1h, w1l, h1, NN);
    agg_csr128<<<(NN * 32 + T - 1) / T, T>>>(h1, a1);

    // 4. layer 2: h2 = relu(a1+b1) @ W2; CSR aggregate + b2 -> out
    mma_gemm<64, true><<<GRID, 256, SMEM2>>>(a1, b1, w2h, w2l, h2, NN);
    agg_csr64<<<(NN * 16 + T - 1) / T, T>>>(h2, b2, out);
}

// round 15
// speedup vs baseline: 2.1400x; 1.0276x over previous
#include <cuda_runtime.h>
#include <cuda_bf16.h>
#include <cstdint>

// Problem constants (fixed by the dataset)
static constexpr int NN  = 100000;   // nodes
static constexpr int NE  = 600000;   // edges
static constexpr int NBLK = (NN + 1023) / 1024;  // 98 scan blocks

// ---------------- scratch (device globals: no allocations allowed) ----------
__device__ int   g_is64;
__device__ int   g_src[NE];
__device__ int   g_dst[NE];
__device__ int   g_cnt[NN];      // in-degree (excl self)
__device__ int   g_rowptr[NN];   // CSR row starts
__device__ int   g_fill[NN];     // scatter fill counters
__device__ int   g_bsum[NBLK];
__device__ int   g_boff[NBLK];
__device__ float g_dinv[NN];
__device__ int   g_csrc[NE];     // CSR-sorted source ids
__device__ float g_cnorm[NE];    // CSR-sorted edge norms
__device__ float g_h1[(size_t)NN * 128];   // x @ W1 (raw)
__device__ float g_a1[(size_t)NN * 128];   // aggregated layer-1
__device__ float g_h2[(size_t)NN * 64];    // relu(a1+b1) @ W2 (raw)
__device__ __nv_bfloat16 g_w1h[128 * 128]; // [n][k] transposed, hi
__device__ __nv_bfloat16 g_w1l[128 * 128];
__device__ __nv_bfloat16 g_w2h[64 * 128];
__device__ __nv_bfloat16 g_w2l[64 * 128];

// ---------------- helpers ----------------------------------------------------
__device__ __forceinline__ uint32_t smem_to_u32(const void* p) {
    uint32_t a;
    asm("{ .reg .u64 t; cvta.to.shared.u64 t, %1; cvt.u32.u64 %0, t; }"
        : "=r"(a) : "l"(p));
    return a;
}
// XOR-swizzle a byte offset within a [rows][256B] tile (16B chunks x row%8)
__device__ __forceinline__ int swz(int o) { return o ^ ((o >> 4) & 0x70); }

__device__ __forceinline__ void ldm_x4(uint32_t* r, uint32_t addr) {
    asm volatile("ldmatrix.sync.aligned.m8n8.x4.shared.b16 {%0,%1,%2,%3}, [%4];"
                 : "=r"(r[0]), "=r"(r[1]), "=r"(r[2]), "=r"(r[3]) : "r"(addr));
}
__device__ __forceinline__ void ldm_x2(uint32_t* r, uint32_t addr) {
    asm volatile("ldmatrix.sync.aligned.m8n8.x2.shared.b16 {%0,%1}, [%2];"
                 : "=r"(r[0]), "=r"(r[1]) : "r"(addr));
}
__device__ __forceinline__ void mma_bf16(float* c, const uint32_t* a, const uint32_t* b) {
    asm volatile(
        "mma.sync.aligned.m16n8k16.row.col.f32.bf16.bf16.f32 "
        "{%0,%1,%2,%3}, {%4,%5,%6,%7}, {%8,%9}, {%0,%1,%2,%3};"
        : "+f"(c[0]), "+f"(c[1]), "+f"(c[2]), "+f"(c[3])
        : "r"(a[0]), "r"(a[1]), "r"(a[2]), "r"(a[3]), "r"(b[0]), "r"(b[1]));
}

__device__ __forceinline__ uint32_t pack_bf2(__nv_bfloat16 a, __nv_bfloat16 b) {
    __nv_bfloat162 t = __halves2bfloat162(a, b);
    return *reinterpret_cast<uint32_t*>(&t);
}
__device__ __forceinline__ void split1(float v, __nv_bfloat16& h, __nv_bfloat16& l) {
    h = __float2bfloat16(v);
    l = __float2bfloat16(v - __bfloat162float(h));
}

// ---------------- edge preprocessing -----------------------------------------
__global__ void detect_kernel(const void* ei) {
    const int* p = (const int*)ei;
    bool z = (p[2 * threadIdx.x + 1] == 0);
    unsigned m = __ballot_sync(0xffffffffu, z);
    __shared__ int ok[2];
    if ((threadIdx.x & 31) == 0) ok[threadIdx.x >> 5] = (m == 0xffffffffu) ? 1 : 0;
    __syncthreads();
    if (threadIdx.x == 0) g_is64 = ok[0] & ok[1];
}

// convert + in-degree count fused
__global__ void convert_count_kernel(const void* ei) {
    int e = blockIdx.x * blockDim.x + threadIdx.x;
    if (e >= NE) return;
    int s, d;
    if (g_is64) {
        const long long* p = (const long long*)ei;
        s = (int)p[e];
        d = (int)p[e + NE];
    } else {
        const int* p = (const int*)ei;
        s = p[e];
        d = p[e + NE];
    }
    g_src[e] = s;
    g_dst[e] = d;
    atomicAdd(&g_cnt[d], 1);
}

// ---------------- CSR build: warp-scan + scatter ------------------------------
__global__ void scan1_kernel() {  // grid NBLK, block 1024
    __shared__ int warpsum[32];
    int b = blockIdx.x, t = threadIdx.x;
    int i = b * 1024 + t;
    int lane = t & 31, w = t >> 5;
    int v = (i < NN) ? g_cnt[i] : 0;
    int x = v;
    #pragma unroll
    for (int off = 1; off < 32; off <<= 1) {
        int y = __shfl_up_sync(0xffffffffu, x, off);
        if (lane >= off) x += y;
    }
    if (lane == 31) warpsum[w] = x;
    __syncthreads();
    if (w == 0) {
        int s = warpsum[lane];
        #pragma unroll
        for (int off = 1; off < 32; off <<= 1) {
            int y = __shfl_up_sync(0xffffffffu, s, off);
            if (lane >= off) s += y;
        }
        warpsum[lane] = s;
    }
    __syncthreads();
    int base = (w > 0) ? warpsum[w - 1] : 0;
    int incl = base + x;
    if (i < NN) g_rowptr[i] = incl - v;   // exclusive within block
    if (t == 1023) g_bsum[b] = incl;
}

__global__ void scan2_kernel() {  // 1 block, 128 threads (NBLK <= 128)
    __shared__ int ws[4];
    int t = threadIdx.x, lane = t & 31, w = t >> 5;
    int v = (t < NBLK) ? g_bsum[t] : 0;
    int x = v;
    #pragma unroll
    for (int off = 1; off < 32; off <<= 1) {
        int y = __shfl_up_sync(0xffffffffu, x, off);
        if (lane >= off) x += y;
    }
    if (lane == 31) ws[w] = x;
    __syncthreads();
    if (t == 0) {
        int run = 0;
        #pragma unroll
        for (int j = 0; j < 4; j++) { int z = ws[j]; ws[j] = run; run += z; }
    }
    __syncthreads();
    if (t < NBLK) g_boff[t] = ws[w] + x - v;   // exclusive
}

// rowptr finalize + dinv fused (same [NN] sweep)
__global__ void scan3_kernel() {
    int i = blockIdx.x * blockDim.x + threadIdx.x;
    if (i < NN) {
        g_rowptr[i] += g_boff[i >> 10];
        g_dinv[i] = rsqrtf((float)g_cnt[i] + 1.0f);
    }
}

__global__ void scatter_kernel() {
    int e = blockIdx.x * blockDim.x + threadIdx.x;
    if (e >= NE) return;
    int s = g_src[e], d = g_dst[e];
    int pos = g_rowptr[d] + atomicAdd(&g_fill[d], 1);
    g_csrc[pos] = s;
    g_cnorm[pos] = g_dinv[s] * g_dinv[d];
}

// both weight matrices: transpose + hi/lo split in one launch
__global__ void wconv_all_kernel(const float* __restrict__ W1,
                                 const float* __restrict__ W2) {
    int i = blockIdx.x * blockDim.x + threadIdx.x;
    if (i < 128 * 128) {
        int k = i >> 7, n = i & 127;   // W1 [k][n], Ncols=128
        __nv_bfloat16 h, l;
        split1(W1[i], h, l);
        g_w1h[n * 128 + k] = h;
        g_w1l[n * 128 + k] = l;
    } else if (i < 128 * 128 + 128 * 64) {
        int j = i - 128 * 128;
        int k = j >> 6, n = j & 63;    // W2 [k][n], Ncols=64
        __nv_bfloat16 h, l;
        split1(W2[j], h, l);
        g_w2h[n * 128 + k] = h;
        g_w2l[n * 128 + k] = l;
    }
}

// ---------------- HMMA GEMM with in-kernel hi/lo split -----------------------
// C[M,NDIM] = op(A)[M,128] @ W[128,NDIM];  op(A) = relu(A + abias) when RELU.
// 3 passes: Ah*Bh + Ah*Bl + Al*Bh, fp32 accum. Epilogue: raw C only.
template <int NDIM, bool RELU>
__global__ void __launch_bounds__(256)
mma_gemm(const float* __restrict__ A, const float* __restrict__ abias,
         const __nv_bfloat16* __restrict__ Bh, const __nv_bfloat16* __restrict__ Bl,
         float* __restrict__ C, int M) {
    extern __shared__ char smem[];
    constexpr int WARP_N = NDIM / 2;   // 64 or 32
    constexpr int NT_N = WARP_N / 8;   // 8 or 4
    constexpr int A_BYTES = 128 * 256;
    constexpr int B_BYTES = NDIM * 256;

    const uint32_t sAh = smem_to_u32(smem);
    const uint32_t sAl = sAh + A_BYTES;
    const uint32_t sB0 = sAl + A_BYTES;
    const uint32_t sB1 = sB0 + B_BYTES;

    const int tid = threadIdx.x, wid = tid >> 5, lane = tid & 31;
    const int warp_row = wid & 3, warp_col = wid >> 2;
    const int rowBase = blockIdx.x * 128;
    const int vr = (M - rowBase < 128) ? (M - rowBase) : 128;

    // ---- A loader: fp32 -> bf16 hi/lo, swizzled SMEM
    {
        const float* gA = A + (size_t)rowBase * 128;
        for (int idx = tid; idx < 128 * 16; idx += 256) {
            int row = idx >> 4, c = idx & 15;
            float4 v0 = make_float4(0.f, 0.f, 0.f, 0.f);
            float4 v1 = v0;
            if (row < vr) {
                v0 = *(const float4*)(gA + (size_t)row * 128 + c * 8);
                v1 = *(const float4*)(gA + (size_t)row * 128 + c * 8 + 4);
            }
            if (RELU) {
                float4 b0 = *(const float4*)(abias + c * 8);
                float4 b1 = *(const float4*)(abias + c * 8 + 4);
                v0.x = fmaxf(v0.x + b0.x, 0.f); v0.y = fmaxf(v0.y + b0.y, 0.f);
                v0.z = fmaxf(v0.z + b0.z, 0.f); v0.w = fmaxf(v0.w + b0.w, 0.f);
                v1.x = fmaxf(v1.x + b1.x, 0.f); v1.y = fmaxf(v1.y + b1.y, 0.f);
                v1.z = fmaxf(v1.z + b1.z, 0.f); v1.w = fmaxf(v1.w + b1.w, 0.f);
            }
            __nv_bfloat16 h[8], l[8];
            split1(v0.x, h[0], l[0]); split1(v0.y, h[1], l[1]);
            split1(v0.z, h[2], l[2]); split1(v0.w, h[3], l[3]);
            split1(v1.x, h[4], l[4]); split1(v1.y, h[5], l[5]);
            split1(v1.z, h[6], l[6]); split1(v1.w, h[7], l[7]);
            int o = swz(row * 256 + c * 16);
            *(uint4*)(smem + o) = make_uint4(
                pack_bf2(h[0], h[1]), pack_bf2(h[2], h[3]),
                pack_bf2(h[4], h[5]), pack_bf2(h[6], h[7]));
            *(uint4*)(smem + A_BYTES + o) = make_uint4(
                pack_bf2(l[0], l[1]), pack_bf2(l[2], l[3]),
                pack_bf2(l[4], l[5]), pack_bf2(l[6], l[7]));
        }
    }
    // ---- B loader
    {
        for (int idx = tid; idx < NDIM * 16; idx += 256) {
            int row = idx >> 4, c = idx & 15;
            int o = swz(row * 256 + c * 16);
            *(uint4*)(smem + 2 * A_BYTES + o) =
                *(const uint4*)(Bh + (size_t)row * 128 + c * 8);
            *(uint4*)(smem + 2 * A_BYTES + B_BYTES + o) =
                *(const uint4*)(Bl + (size_t)row * 128 + c * 8);
        }
    }
    __syncthreads();

    float acc[2][NT_N][4];
    #pragma unroll
    for (int i = 0; i < 2; i++)
        #pragma unroll
        for (int j = 0; j < NT_N; j++)
            #pragma unroll
            for (int q = 0; q < 4; q++) acc[i][j][q] = 0.0f;

    const int at = lane >> 3;
    const int ar = lane & 7;
    const int aRow0 = warp_row * 32 + ar + (at & 1) * 8;
    const int aKt = (at >> 1) * 8;
    const int l15 = lane & 15;
    const int bt = l15 >> 3, br = l15 & 7;
    const int bN0 = warp_col * WARP_N + br;
    const int bKt = bt * 8;

    auto run_pass = [&](uint32_t aBase, uint32_t bBase) {
        #pragma unroll
        for (int ks = 0; ks < 8; ks++) {
            uint32_t a[2][4];
            #pragma unroll
            for (int mi = 0; mi < 2; mi++) {
                int row = aRow0 + mi * 16;
                ldm_x4(a[mi], aBase + swz(row * 256 + (ks * 16 + aKt) * 2));
            }
            uint32_t b[NT_N][2];
            #pragma unroll
            for (int ni = 0; ni < NT_N; ni++) {
                int n = bN0 + ni * 8;
                ldm_x2(b[ni], bBase + swz(n * 256 + (ks * 16 + bKt) * 2));
            }
            #pragma unroll
            for (int mi = 0; mi < 2; mi++)
                #pragma unroll
                for (int ni = 0; ni < NT_N; ni++)
                    mma_bf16(acc[mi][ni], a[mi], b[ni]);
        }
    };

    run_pass(sAh, sB0);   // Ah * Bh
    run_pass(sAh, sB1);   // Ah * Bl
    run_pass(sAl, sB0);   // Al * Bh

    // ---- epilogue: raw C only
    const int erow0 = rowBase + warp_row * 32 + (lane >> 2);
    const int ecol0 = warp_col * WARP_N + (lane & 3) * 2;
    #pragma unroll
    for (int mi = 0; mi < 2; mi++) {
        #pragma unroll
        for (int p = 0; p < 2; p++) {
            int row = erow0 + mi * 16 + p * 8;
            if (row >= M) continue;
            #pragma unroll
            for (int ni = 0; ni < NT_N; ni++) {
                int col = ecol0 + ni * 8;
                *(float2*)(C + (size_t)row * NDIM + col) =
                    make_float2(acc[mi][ni][2 * p], acc[mi][ni][2 * p + 1]);
            }
        }
    }
}

// ---------------- CSR aggregation (gather-only, 2-way MLP) -------------------
// warp per node, 128 features
__global__ void agg_csr128(const float* __restrict__ h, float* __restrict__ out) {
    int t = blockIdx.x * blockDim.x + threadIdx.x;
    int n = t >> 5;
    int lane = t & 31;
    if (n >= NN) return;
    float dv = g_dinv[n];
    float w = dv * dv;
    const float4* hv = (const float4*)h;
    float4 acc = hv[(size_t)n * 32 + lane];
    acc.x *= w; acc.y *= w; acc.z *= w; acc.w *= w;
    float4 acc2 = make_float4(0.f, 0.f, 0.f, 0.f);
    int p = g_rowptr[n];
    int deg = g_cnt[n];
    int j = 0;
    for (; j + 1 < deg; j += 2) {
        int s0 = __ldg(&g_csrc[p + j]);
        int s1 = __ldg(&g_csrc[p + j + 1]);
        float n0 = __ldg(&g_cnorm[p + j]);
        float n1 = __ldg(&g_cnorm[p + j + 1]);
        float4 v0 = hv[(size_t)s0 * 32 + lane];
        float4 v1 = hv[(size_t)s1 * 32 + lane];
        acc.x += v0.x * n0; acc.y += v0.y * n0;
        acc.z += v0.z * n0; acc.w += v0.w * n0;
        acc2.x += v1.x * n1; acc2.y += v1.y * n1;
        acc2.z += v1.z * n1; acc2.w += v1.w * n1;
    }
    if (j < deg) {
        int s0 = __ldg(&g_csrc[p + j]);
        float n0 = __ldg(&g_cnorm[p + j]);
        float4 v0 = hv[(size_t)s0 * 32 + lane];
        acc.x += v0.x * n0; acc.y += v0.y * n0;
        acc.z += v0.z * n0; acc.w += v0.w * n0;
    }
    acc.x += acc2.x; acc.y += acc2.y; acc.z += acc2.z; acc.w += acc2.w;
    ((float4*)out)[(size_t)n * 32 + lane] = acc;
}

// half-warp per node, 64 features; adds bias
__global__ void agg_csr64(const float* __restrict__ h,
                          const float* __restrict__ bias,
                          float* __restrict__ out) {
    int t = blockIdx.x * blockDim.x + threadIdx.x;
    int n = t >> 4;
    int lane = t & 15;
    if (n >= NN) return;
    float dv = g_dinv[n];
    float w = dv * dv;
    const float4* hv = (const float4*)h;
    float4 bb = ((const float4*)bias)[lane];
    float4 acc = hv[(size_t)n * 16 + lane];
    acc.x = acc.x * w + bb.x; acc.y = acc.y * w + bb.y;
    acc.z = acc.z * w + bb.z; acc.w = acc.w * w + bb.w;
    float4 acc2 = make_float4(0.f, 0.f, 0.f, 0.f);
    int p = g_rowptr[n];
    int deg = g_cnt[n];
    int j = 0;
    for (; j + 1 < deg; j += 2) {
        int s0 = __ldg(&g_csrc[p + j]);
        int s1 = __ldg(&g_csrc[p + j + 1]);
        float n0 = __ldg(&g_cnorm[p + j]);
        float n1 = __ldg(&g_cnorm[p + j + 1]);
        float4 v0 = hv[(size_t)s0 * 16 + lane];
        float4 v1 = hv[(size_t)s1 * 16 + lane];
        acc.x += v0.x * n0; acc.y += v0.y * n0;
        acc.z += v0.z * n0; acc.w += v0.w * n0;
        acc2.x += v1.x * n1; acc2.y += v1.y * n1;
        acc2.z += v1.z * n1; acc2.w += v1.w * n1;
    }
    if (j < deg) {
        int s0 = __ldg(&g_csrc[p + j]);
        float n0 = __ldg(&g_cnorm[p + j]);
        float4 v0 = hv[(size_t)s0 * 16 + lane];
        acc.x += v0.x * n0; acc.y += v0.y * n0;
        acc.z += v0.z * n0; acc.w += v0.w * n0;
    }
    acc.x += acc2.x; acc.y += acc2.y; acc.z += acc2.z; acc.w += acc2.w;
    ((float4*)out)[(size_t)n * 16 + lane] = acc;
}

// ---------------- launcher ---------------------------------------------------
extern "C" void kernel_launch(void* const* d_in, const int* in_sizes, int n_in,
                              void* d_out, int out_size) {
    const float* x  = (const float*)d_in[0];
    const void*  ei = d_in[1];
    const float* W1 = (const float*)d_in[2];
    const float* b1 = (const float*)d_in[3];
    const float* W2 = (const float*)d_in[4];
    const float* b2 = (const float*)d_in[5];
    float* out = (float*)d_out;

    float *h1, *a1, *h2;
    int *cntp, *fillp;
    cudaGetSymbolAddress((void**)&h1, g_h1);
    cudaGetSymbolAddress((void**)&a1, g_a1);
    cudaGetSymbolAddress((void**)&h2, g_h2);
    cudaGetSymbolAddress((void**)&cntp, g_cnt);
    cudaGetSymbolAddress((void**)&fillp, g_fill);
    __nv_bfloat16 *w1h, *w1l, *w2h, *w2l;
    cudaGetSymbolAddress((void**)&w1h, g_w1h);
    cudaGetSymbolAddress((void**)&w1l, g_w1l);
    cudaGetSymbolAddress((void**)&w2h, g_w2h);
    cudaGetSymbolAddress((void**)&w2l, g_w2l);

    constexpr int SMEM1 = 2 * 128 * 256 + 2 * 128 * 256;  // 131072
    constexpr int SMEM2 = 2 * 128 * 256 + 2 * 64 * 256;   // 98304
    cudaFuncSetAttribute(mma_gemm<128, false>,
                         cudaFuncAttributeMaxDynamicSharedMemorySize, SMEM1);
    cudaFuncSetAttribute(mma_gemm<64, true>,
                         cudaFuncAttributeMaxDynamicSharedMemorySize, SMEM2);

    const int T = 256;
    // 1. edge preprocessing + CSR build
    cudaMemsetAsync(cntp, 0, NN * sizeof(int));
    cudaMemsetAsync(fillp, 0, NN * sizeof(int));
    detect_kernel<<<1, 64>>>(ei);
    convert_count_kernel<<<(NE + T - 1) / T, T>>>(ei);
    scan1_kernel<<<NBLK, 1024>>>();
    scan2_kernel<<<1, 128>>>();
    scan3_kernel<<<(NN + T - 1) / T, T>>>();
    scatter_kernel<<<(NE + T - 1) / T, T>>>();

    // 2. weight splits (single tiny launch)
    wconv_all_kernel<<<(128 * 128 + 128 * 64 + T - 1) / T, T>>>(W1, W2);

    // 3. layer 1: h1 = x @ W1; CSR aggregate (self + edges) -> a1
    const int GRID = (NN + 127) / 128;  // 782
    mma_gemm<128, false><<<GRID, 256, SMEM1>>>(x, nullptr, w1h, w1l, h1, NN);
    agg_csr128<<<(NN * 32 + T - 1) / T, T>>>(h1, a1);

    // 4. layer 2: h2 = relu(a1+b1) @ W2; CSR aggregate + b2 -> out
    mma_gemm<64, true><<<GRID, 256, SMEM2>>>(a1, b1, w2h, w2l, h2, NN);
    agg_csr64<<<(NN * 16 + T - 1) / T, T>>>(h2, b2, out);
}